// round 2
// baseline (speedup 1.0000x reference)
#include <cuda_runtime.h>
#include <cuda_bf16.h>
#include <math_constants.h>

// Problem constants (fixed by the dataset)
#define BQ      1024       // queries
#define DD      128        // dim
#define TOPK    8
#define NCHUNKS 74         // key chunks (grid.x) -> 74*8 = 592 CTAs = 4 full waves
#define QT      128        // queries per CTA
#define KT      64         // keys per tile
#define SMP     65         // sims row pitch (bank-conflict-free scan)

// Scratch (no cudaMalloc allowed)
__device__ float g_qn[BQ * DD];                    // normalized queries
__device__ float g_rk[500032];                     // 1/||k||
__device__ float g_cs[BQ * NCHUNKS * TOPK];        // per-chunk candidate scores
__device__ int   g_ci[BQ * NCHUNKS * TOPK];        // per-chunk candidate indices

// ---------------- query normalization ----------------
__global__ void normq_kernel(const float* __restrict__ q) {
    int b = blockIdx.x;
    int t = threadIdx.x;                 // 128 threads, one per dim
    float v = q[b * DD + t];
    float s = v * v;
    #pragma unroll
    for (int off = 16; off; off >>= 1) s += __shfl_xor_sync(0xffffffff, s, off);
    __shared__ float ws[4];
    if ((t & 31) == 0) ws[t >> 5] = s;
    __syncthreads();
    float tot = ws[0] + ws[1] + ws[2] + ws[3];
    float inv = 1.0f / fmaxf(sqrtf(tot), 1e-12f);
    g_qn[b * DD + t] = v * inv;
}

// ---------------- key reciprocal norms ----------------
__global__ void rnormk_kernel(const float* __restrict__ keys, int N) {
    int gw = (blockIdx.x * blockDim.x + threadIdx.x) >> 5;  // one warp per key row
    int lane = threadIdx.x & 31;
    if (gw >= N) return;
    float4 v = *(const float4*)(keys + (size_t)gw * DD + lane * 4);
    float s = v.x * v.x + v.y * v.y + v.z * v.z + v.w * v.w;
    #pragma unroll
    for (int off = 16; off; off >>= 1) s += __shfl_xor_sync(0xffffffff, s, off);
    if (lane == 0) g_rk[gw] = 1.0f / fmaxf(sqrtf(s), 1e-12f);
}

// sorted-descending branch-free top-8 insert (register resident, fully unrolled)
__device__ __forceinline__ void insert_top8(float (&ts)[TOPK], int (&ti)[TOPK],
                                            float s, int id) {
    #pragma unroll
    for (int j = TOPK - 1; j >= 1; j--) {
        if (ts[j] < s) {
            bool here = ts[j - 1] >= s;
            ts[j] = here ? s : ts[j - 1];
            ti[j] = here ? id : ti[j - 1];
        }
    }
    if (ts[0] < s) { ts[0] = s; ti[0] = id; }
}

// ---------------- fused sim-GEMM + per-chunk top-8 ----------------
// grid: (NCHUNKS, B/QT), block: 256
// smem: qs[128][128] d-major | ks[128][64] d-major | sm[128][65] | rks[64]
#define SH_QS 0
#define SH_KS 16384
#define SH_SM 24576
#define SH_RK (24576 + QT * SMP)
#define SMEM_FLOATS (SH_RK + KT)
#define SMEM_BYTES  (SMEM_FLOATS * 4)

__global__ void __launch_bounds__(256, 1)
simtopk_kernel(const float* __restrict__ keys, int N, int CH) {
    extern __shared__ float sh[];
    float* qs  = sh + SH_QS;
    float* ks  = sh + SH_KS;
    float* sm  = sh + SH_SM;
    float* rks = sh + SH_RK;

    const int tid = threadIdx.x;
    const int qBase = blockIdx.y * QT;
    const int c0 = blockIdx.x * CH;
    const int c1 = min(c0 + CH, N);

    // Load q tile transposed to d-major: qs[d][q]. Coalesced global float4.
    for (int i = tid; i < 32 * QT; i += 256) {
        int d4 = i >> 7;            // 0..31
        int q  = i & 127;
        float4 v = *(const float4*)(g_qn + (size_t)(qBase + q) * DD + d4 * 4);
        qs[(d4 * 4 + 0) * QT + q] = v.x;
        qs[(d4 * 4 + 1) * QT + q] = v.y;
        qs[(d4 * 4 + 2) * QT + q] = v.z;
        qs[(d4 * 4 + 3) * QT + q] = v.w;
    }

    const int tx = tid & 15;        // key group:   k = tx*4 + i
    const int ty = tid >> 4;        // query group: q = ty*8 + j

    float ts[TOPK];
    int   ti[TOPK];
    #pragma unroll
    for (int j = 0; j < TOPK; j++) { ts[j] = -CUDART_INF_F; ti[j] = 0; }

    __syncthreads();

    for (int n0 = c0; n0 < c1; n0 += KT) {
        const int kc = min(KT, c1 - n0);

        // Load key tile transposed to d-major: ks[d][k]. (bank-conflict-free stores)
        for (int i = tid; i < 32 * KT; i += 256) {
            int d4 = i >> 6;        // 0..31
            int k  = i & 63;
            float4 v = make_float4(0.f, 0.f, 0.f, 0.f);
            if (k < kc) v = *(const float4*)(keys + (size_t)(n0 + k) * DD + d4 * 4);
            ks[(d4 * 4 + 0) * KT + k] = v.x;
            ks[(d4 * 4 + 1) * KT + k] = v.y;
            ks[(d4 * 4 + 2) * KT + k] = v.z;
            ks[(d4 * 4 + 3) * KT + k] = v.w;
        }
        if (tid < KT) rks[tid] = (tid < kc) ? g_rk[n0 + tid] : 0.f;
        __syncthreads();   // A: ks/rks ready; prior-tile scan complete before sm rewrite

        // Register-tiled 128x64 fp32 GEMM over d=0..127
        float acc[8][4];
        #pragma unroll
        for (int j = 0; j < 8; j++)
            #pragma unroll
            for (int i = 0; i < 4; i++) acc[j][i] = 0.f;

        #pragma unroll 4
        for (int d = 0; d < DD; d++) {
            float4 bb = *(const float4*)(ks + d * KT + tx * 4);
            float4 a0 = *(const float4*)(qs + d * QT + ty * 8);
            float4 a1 = *(const float4*)(qs + d * QT + ty * 8 + 4);
            float av[8] = {a0.x, a0.y, a0.z, a0.w, a1.x, a1.y, a1.z, a1.w};
            #pragma unroll
            for (int j = 0; j < 8; j++) {
                acc[j][0] += av[j] * bb.x;
                acc[j][1] += av[j] * bb.y;
                acc[j][2] += av[j] * bb.z;
                acc[j][3] += av[j] * bb.w;
            }
        }

        // Scale by 1/||k|| and stage sims tile
        float4 rr = *(const float4*)(rks + tx * 4);
        float rv[4] = {rr.x, rr.y, rr.z, rr.w};
        #pragma unroll
        for (int j = 0; j < 8; j++)
            #pragma unroll
            for (int i = 0; i < 4; i++)
                sm[(ty * 8 + j) * SMP + tx * 4 + i] = acc[j][i] * rv[i];
        __syncthreads();   // B: sims visible; compute reads of ks done before next load

        // Per-query top-8 scan (threads 0..127, conflict-free via SMP=65)
        if (tid < QT) {
            const float* row = sm + tid * SMP;
            float mn = ts[TOPK - 1];
            for (int k = 0; k < kc; k++) {
                float s = row[k];
                if (s > mn) { insert_top8(ts, ti, s, n0 + k); mn = ts[TOPK - 1]; }
            }
        }
        // no barrier needed: next iteration's sync A orders scan before sm rewrite
    }

    if (tid < QT) {
        int q = qBase + tid;
        size_t base = ((size_t)q * NCHUNKS + blockIdx.x) * TOPK;
        #pragma unroll
        for (int j = 0; j < TOPK; j++) { g_cs[base + j] = ts[j]; g_ci[base + j] = ti[j]; }
    }
}

// ---------------- merge per-chunk candidates + gather values ----------------
__global__ void merge_gather_kernel(const float* __restrict__ values,
                                    float* __restrict__ out) {
    const int q = blockIdx.x;
    const int tid = threadIdx.x;
    const int TOT = NCHUNKS * TOPK;    // 592
    __shared__ float cs[NCHUNKS * TOPK];
    __shared__ int   ci[NCHUNKS * TOPK];
    __shared__ int   sel[TOPK];

    for (int i = tid; i < TOT; i += 256) {
        cs[i] = g_cs[(size_t)q * TOT + i];
        ci[i] = g_ci[(size_t)q * TOT + i];
    }
    __syncthreads();

    if (tid < 32) {
        for (int r = 0; r < TOPK; r++) {
            float bs = -CUDART_INF_F; int bi = 0x7fffffff; int bj = 0;
            for (int i = tid; i < TOT; i += 32) {
                float s = cs[i]; int ix = ci[i];
                if (s > bs || (s == bs && ix < bi)) { bs = s; bi = ix; bj = i; }
            }
            #pragma unroll
            for (int off = 16; off; off >>= 1) {
                float os = __shfl_xor_sync(0xffffffff, bs, off);
                int   oi = __shfl_xor_sync(0xffffffff, bi, off);
                int   oj = __shfl_xor_sync(0xffffffff, bj, off);
                if (os > bs || (os == bs && oi < bi)) { bs = os; bi = oi; bj = oj; }
            }
            if (tid == 0) { sel[r] = bi; cs[bj] = -CUDART_INF_F; }
            __syncwarp();
        }
    }
    __syncthreads();

    for (int i = tid; i < TOPK * DD; i += 256) {
        int r = i >> 7, d = i & 127;
        out[((size_t)q * TOPK + r) * DD + d] = values[(size_t)sel[r] * DD + d];
    }
}

// ---------------- launch ----------------
extern "C" void kernel_launch(void* const* d_in, const int* in_sizes, int n_in,
                              void* d_out, int out_size) {
    const float* q_emb = (const float*)d_in[0];
    const float* keys  = (const float*)d_in[1];
    const float* vals  = (const float*)d_in[2];
    float* out = (float*)d_out;

    int B = in_sizes[0] / DD;        // 1024
    int N = in_sizes[1] / DD;        // 500000
    int CH = (N + NCHUNKS - 1) / NCHUNKS;

    normq_kernel<<<B, 128>>>(q_emb);
    rnormk_kernel<<<(N + 7) / 8, 256>>>(keys, N);

    cudaFuncSetAttribute(simtopk_kernel,
                         cudaFuncAttributeMaxDynamicSharedMemorySize, SMEM_BYTES);
    dim3 grid(NCHUNKS, B / QT);
    simtopk_kernel<<<grid, 256, SMEM_BYTES>>>(keys, N, CH);

    merge_gather_kernel<<<B, 256>>>(vals, out);
}